// round 17
// baseline (speedup 1.0000x reference)
#include <cuda_runtime.h>
#include <cuda_bf16.h>
#include <cstdint>

// ============================================================================
// NeRF fused MLP on tcgen05, R16: cta_group::2 (2-CTA MMA) pipeline.
// Cluster (2,1,1): the pair computes M=256 per chunk (each CTA owns its 128
// points). B is split N/2=128 cols per CTA -> per-CTA weight copy halves to
// 8KB/chunk (the R13-15 binding constraint was the chip-wide L2 weight
// stream at the ~6.3KB/cyc LTS cap). 8 x 8KB B buffers, prefetch distance 7.
// Roles per CTA: tid32 copy producer (cp.async.bulk -> local cfull[b]),
// tid64 forwarder (wait cfull[b] -> arrive leader ready[b], count 2),
// rank0 tid0 MMA issuer (wait ready[b] -> 3 cg2 MMAs -> multicast commit
// mma[b]); layer completion via multicast commit to both CTAs' layer bar.
// Per layer: drain -> 16-warp epilogue (LDTM f32 + bias(__ldg) + ReLU +
// bf16 hi/lo split -> local A tiles, sigma fold on g2_2) -> CLUSTER_SYNC.
// Heads (sigma partials + 16-warp rgb) unchanged, all local.
// ============================================================================

#if defined(__CUDA_ARCH_FEAT_SM103_ALL) || defined(__CUDA_ARCH_FEAT_SM100_ALL) || defined(__CUDA_ARCH_FEAT_SM101_ALL)
#define HAS_TC 1
#else
#define HAS_TC 0
#endif

#define TPB        512
#define MROWS      128
#define NBUF       8
#define AHI_OFF    0
#define ALO_OFF    81920
#define B_OFF      163840            // 8 x 8KB buffers = 64KB
#define TMEMP_OFF  229376
#define MBAR_OFF   229384            // cfull[8]@+0, mmaf[8]@+64, layer@+128, ready[8]@+136
#define SIGW_OFF   229600            // 1KB sig_W (16B aligned)
#define SIGA_OFF   230624            // 512B per-row sigma partials
#define SMEM_BYTES 231136
#define CH_STRIDE  16384u            // scratch stride per chunk (both ranks)
#define CPY_BYTES  8192u             // per-CTA copy (its N-half)
#define NCH_TOTAL  140
// idesc kind::f16 cg2: dtype=F32(1<<4), a=BF16(1<<7), b=BF16(1<<10),
// N=256 -> (256/8)<<17, M=256 -> (256/16)<<24
#define IDESC2     0x10400490u
#define WSCRATCH_BYTES (NCH_TOTAL * CH_STRIDE)

__device__ __align__(128) unsigned char g_wscratch[WSCRATCH_BYTES];

static __device__ __forceinline__ uint32_t swz128(uint32_t b) { return b ^ ((b >> 3) & 0x70); }
static __device__ __forceinline__ uint32_t swz64(uint32_t b)  { return b ^ ((b >> 3) & 0x30); }
// A tile (SW128 blocked atoms, 128 rows x 320 K-cols)
static __device__ __forceinline__ uint32_t tile_off(int r, int k) {
    return (uint32_t)(((k >> 6) * 16 + (r >> 3)) * 1024)
         + swz128((uint32_t)(((r & 7) << 7) | ((k & 63) << 1)));
}
// B chunk frame (SW64, 128 local N-rows x 32 K-cols bf16 = 64B rows, 8KB)
static __device__ __forceinline__ uint32_t b_off64(int n, int c) {
    return (uint32_t)((n >> 3) * 512)
         + swz64((uint32_t)(((n & 7) << 6) | (c << 1)));
}
static __device__ __forceinline__ uint32_t smem_u32(const void* p) {
    uint32_t a;
    asm("{ .reg .u64 t; cvta.to.shared.u64 t, %1; cvt.u32.u64 %0, t; }" : "=r"(a) : "l"(p));
    return a;
}
static __device__ __forceinline__ uint32_t cluster_rank() {
    uint32_t r; asm("mov.u32 %0, %%cluster_ctarank;" : "=r"(r)); return r;
}
static __device__ __forceinline__ uint64_t mkdesc128(uint32_t addr) {
    const uint64_t base = (uint64_t(2) << 61) | (uint64_t(1) << 46)
                        | (uint64_t(64) << 32) | (uint64_t(1) << 16);
    return base | ((uint64_t)(addr >> 4) & 0x3FFF);
}
static __device__ __forceinline__ uint64_t mkdesc64(uint32_t addr) {
    const uint64_t base = (uint64_t(4) << 61) | (uint64_t(1) << 46)
                        | (uint64_t(32) << 32) | (uint64_t(1) << 16);
    return base | ((uint64_t)(addr >> 4) & 0x3FFF);
}

static __device__ __forceinline__ void mma_cg2(uint32_t d, uint64_t ad, uint64_t bd, uint32_t en) {
#if HAS_TC
    asm volatile(
        "{ .reg .pred p; setp.ne.u32 p, %5, 0;\n\t"
        "tcgen05.mma.cta_group::2.kind::f16 [%0], %1, %2, %3, {%4,%4,%4,%4,%4,%4,%4,%4}, p; }"
        :: "r"(d), "l"(ad), "l"(bd), "r"(IDESC2), "r"(0u), "r"(en) : "memory");
#endif
}
static __device__ __forceinline__ void mbar_init(uint32_t a, uint32_t cnt) {
    asm volatile("mbarrier.init.shared.b64 [%0], %1;" :: "r"(a), "r"(cnt) : "memory");
}
// arrive on the LEADER (rank0) CTA's barrier at the same offset (bit 24 clear)
static __device__ __forceinline__ void mbar_arrive_leader(uint32_t a) {
    asm volatile(
        "{ .reg .b32 la; and.b32 la, %0, 0xFEFFFFFF;\n\t"
        "mbarrier.arrive.shared::cluster.b64 _, [la]; }"
        :: "r"(a) : "memory");
}
static __device__ __forceinline__ void mbar_expect_tx(uint32_t a, uint32_t bytes) {
    asm volatile("mbarrier.arrive.expect_tx.shared.b64 _, [%0], %1;" :: "r"(a), "r"(bytes) : "memory");
}
static __device__ __forceinline__ void bulk_copy8k(uint32_t dst, const void* src, uint32_t mbar) {
    asm volatile(
        "cp.async.bulk.shared::cluster.global.mbarrier::complete_tx::bytes [%0], [%1], %2, [%3];"
        :: "r"(dst), "l"(src), "r"(CPY_BYTES), "r"(mbar) : "memory");
}
static __device__ __forceinline__ void mbar_wait(uint32_t a, uint32_t parity) {
    uint32_t done;
    asm volatile(
        "{ .reg .pred p; mbarrier.try_wait.parity.acquire.cta.shared::cta.b64 p, [%1], %2;"
        " selp.b32 %0, 1, 0, p; }" : "=r"(done) : "r"(a), "r"(parity) : "memory");
    if (!done) {
        asm volatile(
            "{ .reg .pred P1;\n\t"
            "WL%=:\n\t"
            "mbarrier.try_wait.parity.acquire.cta.shared::cta.b64 P1, [%0], %1, 0x989680;\n\t"
            "@P1 bra WD%=;\n\t"
            "bra WL%=;\n\t"
            "WD%=:\n\t}" :: "r"(a), "r"(parity) : "memory");
    }
}
#define CLUSTER_SYNC() do { \
    asm volatile("barrier.cluster.arrive.aligned;" ::: "memory"); \
    asm volatile("barrier.cluster.wait.aligned;" ::: "memory"); \
} while (0)

#if HAS_TC
#define TC_ALLOC2(sa, n)  asm volatile("tcgen05.alloc.cta_group::2.sync.aligned.shared::cta.b32 [%0], %1;" :: "r"(sa), "r"(n) : "memory")
#define TC_RELINQ2()      asm volatile("tcgen05.relinquish_alloc_permit.cta_group::2.sync.aligned;")
#define TC_DEALLOC2(t, n) asm volatile("tcgen05.dealloc.cta_group::2.sync.aligned.b32 %0, %1;" :: "r"(t), "r"(n))
#define TC_COMMIT_MC2(mb) asm volatile("tcgen05.commit.cta_group::2.mbarrier::arrive::one.shared::cluster.multicast::cluster.b64 [%0], %1;" :: "r"(mb), "h"((unsigned short)0x3) : "memory")
#define TC_FENCE_AFTER()  asm volatile("tcgen05.fence::after_thread_sync;" ::: "memory")
#define TC_FENCE_BEFORE() asm volatile("tcgen05.fence::before_thread_sync;" ::: "memory")
#define TC_WAIT_LD()      asm volatile("tcgen05.wait::ld.sync.aligned;" ::: "memory")
#define TC_LD_X32(r, ta) \
    asm volatile( \
        "tcgen05.ld.sync.aligned.32x32b.x32.b32 " \
        "{%0, %1, %2, %3, %4, %5, %6, %7, " \
        " %8, %9, %10, %11, %12, %13, %14, %15, " \
        " %16, %17, %18, %19, %20, %21, %22, %23, " \
        " %24, %25, %26, %27, %28, %29, %30, %31}, [%32];" \
        : "=r"((r)[0]),  "=r"((r)[1]),  "=r"((r)[2]),  "=r"((r)[3]), \
          "=r"((r)[4]),  "=r"((r)[5]),  "=r"((r)[6]),  "=r"((r)[7]), \
          "=r"((r)[8]),  "=r"((r)[9]),  "=r"((r)[10]), "=r"((r)[11]), \
          "=r"((r)[12]), "=r"((r)[13]), "=r"((r)[14]), "=r"((r)[15]), \
          "=r"((r)[16]), "=r"((r)[17]), "=r"((r)[18]), "=r"((r)[19]), \
          "=r"((r)[20]), "=r"((r)[21]), "=r"((r)[22]), "=r"((r)[23]), \
          "=r"((r)[24]), "=r"((r)[25]), "=r"((r)[26]), "=r"((r)[27]), \
          "=r"((r)[28]), "=r"((r)[29]), "=r"((r)[30]), "=r"((r)[31]) \
        : "r"(ta))
#else
#define TC_ALLOC2(sa, n)  ((void)0)
#define TC_RELINQ2()      ((void)0)
#define TC_DEALLOC2(t, n) ((void)0)
#define TC_COMMIT_MC2(mb) ((void)0)
#define TC_FENCE_AFTER()  ((void)0)
#define TC_FENCE_BEFORE() ((void)0)
#define TC_WAIT_LD()      ((void)0)
#define TC_LD_X32(r, ta)  do { _Pragma("unroll") for (int _i = 0; _i < 32; ++_i) (r)[_i] = 0u; } while (0)
#endif
#define FENCE_ASYNC()     asm volatile("fence.proxy.async;" ::: "memory")

// packed split: hp = bf16x2(v0,v1) (lo=v0), lp = bf16x2 of residuals
static __device__ __forceinline__ void split2(float v0, float v1, uint32_t& hp, uint32_t& lp) {
    asm("cvt.rn.bf16x2.f32 %0, %1, %2;" : "=r"(hp) : "f"(v1), "f"(v0));
    float h0 = __uint_as_float(hp << 16);
    float h1 = __uint_as_float(hp & 0xffff0000u);
    float l0 = v0 - h0, l1 = v1 - h1;
    asm("cvt.rn.bf16x2.f32 %0, %1, %2;" : "=r"(lp) : "f"(l1), "f"(l0));
}

static __device__ __forceinline__ void a_store(char* Ahi, char* Alo, int r, int k, float v) {
    __nv_bfloat16 h = __float2bfloat16(v);
    float l = v - __bfloat162float(h);
    uint32_t o = tile_off(r, k);
    *(__nv_bfloat16*)(Ahi + o) = h;
    *(__nv_bfloat16*)(Alo + o) = __float2bfloat16(l);
}

// -------------------------------------------------------------- prepass -----
// Chunk bases: L0@0(4), L1@4, L2@20, L3@36, L4@52, L5@68(20), L6@88, L7@104,
// L8@120(20). Total 140. Each 16KB chunk = [rank0 N-cols 0-127: 8KB]
// [rank1 N-cols 128-255: 8KB], per-rank frame = SW64, hi cols [0,16), lo [16,32).
__global__ void nerf_prepass(
    const float* W0, const float* W1, const float* W2, const float* W3, const float* W4,
    const float* W5, const float* W6, const float* W7, const float* W8)
{
    int layer = blockIdx.y;
    int k = blockIdx.x;           // padded K index within layer
    int n = threadIdx.x;          // output neuron 0..255
    const float* W; int Kpad, kaoff, kalen, kblen; uint32_t cbase;
    switch (layer) {
        case 0: W = W0; Kpad = 64;  kaoff = 0;  kalen = 63;  kblen = 0;   cbase = 0;   break;
        case 1: W = W1; Kpad = 256; kaoff = 0;  kalen = 256; kblen = 0;   cbase = 4;   break;
        case 2: W = W2; Kpad = 256; kaoff = 0;  kalen = 256; kblen = 0;   cbase = 20;  break;
        case 3: W = W3; Kpad = 256; kaoff = 0;  kalen = 256; kblen = 0;   cbase = 36;  break;
        case 4: W = W4; Kpad = 256; kaoff = 0;  kalen = 256; kblen = 0;   cbase = 52;  break;
        case 5: W = W5; Kpad = 320; kaoff = 0;  kalen = 63;  kblen = 256; cbase = 68;  break;
        case 6: W = W6; Kpad = 256; kaoff = 0;  kalen = 256; kblen = 0;   cbase = 88;  break;
        case 7: W = W7; Kpad = 256; kaoff = 0;  kalen = 256; kblen = 0;   cbase = 104; break;
        default: W = W8; Kpad = 320; kaoff = 24; kalen = 39; kblen = 256; cbase = 120; break;
    }
    if (k >= Kpad) return;
    int row = -1;
    if (k >= kaoff && k < kaoff + kalen) row = k - kaoff;
    else if (kblen && k >= 64 && k < 64 + kblen) row = kalen + (k - 64);
    float v = (row >= 0) ? W[(size_t)row * 256 + n] : 0.f;

    uint32_t off = (cbase + (uint32_t)(k >> 4)) * CH_STRIDE + (uint32_t)(n >> 7) * CPY_BYTES;
    int nl = n & 127;
    int local = k & 15;
    __nv_bfloat16 h = __float2bfloat16(v);
    float l = v - __bfloat162float(h);
    *(__nv_bfloat16*)(g_wscratch + off + b_off64(nl, local))      = h;
    *(__nv_bfloat16*)(g_wscratch + off + b_off64(nl, 16 + local)) = __float2bfloat16(l);
}

// ------------------------------------------------------------- run_layer ----
struct Pipe {
    int gmma, gcopy, gfwd, lpar;
    int rpf[NBUF];   // issuer: ready[] parity
    int pm[NBUF];    // copy thread: mmaf[] parity
    int pc[NBUF];    // forwarder: cfull[] parity
};

static __device__ __noinline__ void run_layer(
    char* smem, uint32_t sb, uint32_t tmem, uint32_t rank,
    int nch, int a_step0,
    const float* __restrict__ bias, int relu, int do_epi, int do_sig, Pipe& pp)
{
    const int tid = threadIdx.x;
    const int w = tid >> 5;

    if (rank == 0 && tid == 0) {
        // ---- MMA issuer (pair leader): wait ready (both halves) -> 3 cg2 MMAs.
        const uint64_t adh = mkdesc128(sb + AHI_OFF);
        const uint64_t adl = mkdesc128(sb + ALO_OFF);
        for (int i = 0; i < nch; ++i) {
            const int t = pp.gmma++;
            const int b = t & (NBUF - 1);
            mbar_wait(sb + MBAR_OFF + 136 + b * 8, (uint32_t)pp.rpf[b]);
            pp.rpf[b] ^= 1;
            const uint64_t bd = mkdesc64(sb + B_OFF + (uint32_t)b * CPY_BYTES);
            const int s = a_step0 + i;
            const uint64_t aoff = (uint64_t)((s >> 2) * 1024 + (s & 3) * 2);
            mma_cg2(tmem, adh + aoff, bd,     i > 0);  // Ahi*Bhi
            mma_cg2(tmem, adh + aoff, bd + 2, 1u);     // Ahi*Blo
            mma_cg2(tmem, adl + aoff, bd,     1u);     // Alo*Bhi
            TC_COMMIT_MC2(sb + MBAR_OFF + 64 + b * 8); // mma-free -> both CTAs
        }
        TC_COMMIT_MC2(sb + MBAR_OFF + 128);            // layer-done -> both CTAs
    } else if (tid == 32) {
        // ---- Copy producer: per-CTA 8KB half-chunks, prefetch distance 7.
        for (int i = 0; i < nch; ++i) {
            const int t = pp.gcopy;
            if (t >= NCH_TOTAL) break;
            const int b = t & (NBUF - 1);
            if (t >= NBUF) {   // chunk t-8 used this buffer; wait MMAs drained
                mbar_wait(sb + MBAR_OFF + 64 + b * 8, (uint32_t)pp.pm[b]);
                pp.pm[b] ^= 1;
            }
            mbar_expect_tx(sb + MBAR_OFF + b * 8, CPY_BYTES);
            bulk_copy8k(sb + B_OFF + (uint32_t)b * CPY_BYTES,
                        g_wscratch + (uint32_t)t * CH_STRIDE + rank * CPY_BYTES,
                        sb + MBAR_OFF + b * 8);
            pp.gcopy = t + 1;
        }
    } else if (tid == 64) {
        // ---- Forwarder: local copy done -> arrive leader ready[b] (count 2).
        for (int i = 0; i < nch; ++i) {
            const int t = pp.gfwd++;
            const int b = t & (NBUF - 1);
            mbar_wait(sb + MBAR_OFF + b * 8, (uint32_t)pp.pc[b]);
            pp.pc[b] ^= 1;
            mbar_arrive_leader(sb + MBAR_OFF + 136 + b * 8);
        }
    }

    // all threads: wait layer completion (fired by multicast commit)
    mbar_wait(sb + MBAR_OFF + 128, (uint32_t)pp.lpar);
    pp.lpar ^= 1;
    TC_FENCE_AFTER();
    if (!do_epi) return;

    // ---- 16-warp epilogue on LOCAL TMEM D (this CTA's 128 rows)
    const int lane = tid & 31;
    const int r  = (w & 3) * 32 + lane;
    const int c0 = (w >> 2) * 64;
    char* Ahi = smem + AHI_OFF;
    char* Alo = smem + ALO_OFF;
    const float* sw = (const float*)(smem + SIGW_OFF);
    float sg = 0.f;

    #pragma unroll
    for (int h = 0; h < 2; ++h) {
        const int kb = c0 + h * 32;
        float4 bb[8];
        #pragma unroll
        for (int q = 0; q < 8; ++q) bb[q] = __ldg((const float4*)bias + kb / 4 + q);
        uint32_t rg[32];
        TC_LD_X32(rg, tmem + kb);
        TC_WAIT_LD();
        #pragma unroll
        for (int q = 0; q < 4; ++q) {
            float4 b0 = bb[2 * q];
            float4 b1 = bb[2 * q + 1];
            float v[8];
            v[0] = __uint_as_float(rg[q * 8 + 0]) + b0.x;
            v[1] = __uint_as_float(rg[q * 8 + 1]) + b0.y;
            v[2] = __uint_as_float(rg[q * 8 + 2]) + b0.z;
            v[3] = __uint_as_float(rg[q * 8 + 3]) + b0.w;
            v[4] = __uint_as_float(rg[q * 8 + 4]) + b1.x;
            v[5] = __uint_as_float(rg[q * 8 + 5]) + b1.y;
            v[6] = __uint_as_float(rg[q * 8 + 6]) + b1.z;
            v[7] = __uint_as_float(rg[q * 8 + 7]) + b1.w;
            if (relu) {
                #pragma unroll
                for (int e = 0; e < 8; ++e) v[e] = fmaxf(v[e], 0.f);
            }
            if (do_sig) {
                #pragma unroll
                for (int e = 0; e < 8; ++e) sg += v[e] * sw[kb + q * 8 + e];
            }
            uint32_t hp[4], lp[4];
            #pragma unroll
            for (int e = 0; e < 4; ++e) split2(v[2 * e], v[2 * e + 1], hp[e], lp[e]);
            uint32_t off = tile_off(r, 64 + kb + q * 8);
            *(uint4*)(Ahi + off) = make_uint4(hp[0], hp[1], hp[2], hp[3]);
            *(uint4*)(Alo + off) = make_uint4(lp[0], lp[1], lp[2], lp[3]);
        }
    }
    if (do_sig) atomicAdd((float*)(smem + SIGA_OFF) + r, sg);
    TC_FENCE_BEFORE();
    FENCE_ASYNC();     // A writes visible to async proxy (peer MMA reads)
    CLUSTER_SYNC();    // both CTAs' A tiles ready before next layer's MMAs
}

// ----------------------------------------------------------- main kernel ----
__global__ void __launch_bounds__(TPB, 1) __cluster_dims__(2, 1, 1) nerf_main(
    const float* __restrict__ x, const float* __restrict__ dirg,
    const float* g1_0_b, const float* g1_1_b, const float* g1_2_b,
    const float* g1_3_b, const float* g1_4_b,
    const float* g2_0_b, const float* g2_1_b, const float* g2_2_b,
    const float* c_0_b,  const float* c_1_W,  const float* c_1_b,
    const float* sig_W,  const float* sig_b,
    float* __restrict__ out)
{
    extern __shared__ __align__(1024) char smem[];
    const uint32_t sb = smem_u32(smem);
    const int tid = threadIdx.x;
    const int w = tid >> 5, lane = tid & 31;
    const uint32_t rank = cluster_rank();
    char* Ahi = smem + AHI_OFF;
    char* Alo = smem + ALO_OFF;

    if (w == 0) TC_ALLOC2(sb + TMEMP_OFF, 256);
    if (tid == 0) {
        #pragma unroll
        for (int b = 0; b < NBUF; ++b) {
            mbar_init(sb + MBAR_OFF + b * 8, 1);          // cfull[b]
            mbar_init(sb + MBAR_OFF + 64 + b * 8, 1);     // mmaf[b]
            mbar_init(sb + MBAR_OFF + 136 + b * 8, 2);    // ready[b] (leader-used)
        }
        mbar_init(sb + MBAR_OFF + 128, 1);                // layer
        FENCE_ASYNC();
    }
    // stage sig_W + zero sigma partials (once)
    if (tid < 64) ((float4*)(smem + SIGW_OFF))[tid] = __ldg((const float4*)sig_W + tid);
    if (tid < 128) ((float*)(smem + SIGA_OFF))[tid] = 0.f;
    __syncthreads();
    CLUSTER_SYNC();    // barriers initialized cluster-wide before any remote op

    // prologue: 7 half-chunks in flight during PE computation
    if (tid == 32) {
        #pragma unroll
        for (int t = 0; t < NBUF - 1; ++t) {
            mbar_expect_tx(sb + MBAR_OFF + t * 8, CPY_BYTES);
            bulk_copy8k(sb + B_OFF + (uint32_t)t * CPY_BYTES,
                        g_wscratch + (uint32_t)t * CH_STRIDE + rank * CPY_BYTES,
                        sb + MBAR_OFF + t * 8);
        }
    }
    uint32_t tmem;
    asm volatile("ld.shared.b32 %0, [%1];" : "=r"(tmem) : "r"(sb + TMEMP_OFF));

    const int row0 = blockIdx.x * MROWS;
    const int r = tid >> 2, p = tid & 3;

    if (tid < 128) a_store(Ahi, Alo, tid, 63, 0.f);

    {
        const float* xr = x + (size_t)(row0 + r) * 3;
        float x0 = xr[0], x1 = xr[1], x2 = xr[2];
        if (p == 0) {
            a_store(Ahi, Alo, r, 0, x0);
            a_store(Ahi, Alo, r, 1, x1);
            a_store(Ahi, Alo, r, 2, x2);
        }
        for (int l = p; l < 10; l += 4) {
            float f = (float)(1 << l);
            float s, c;
            sincosf(x0 * f, &s, &c); a_store(Ahi, Alo, r, 3 + 6 * l + 0, s); a_store(Ahi, Alo, r, 6 + 6 * l + 0, c);
            sincosf(x1 * f, &s, &c); a_store(Ahi, Alo, r, 3 + 6 * l + 1, s); a_store(Ahi, Alo, r, 6 + 6 * l + 1, c);
            sincosf(x2 * f, &s, &c); a_store(Ahi, Alo, r, 3 + 6 * l + 2, s); a_store(Ahi, Alo, r, 6 + 6 * l + 2, c);
        }
    }
    FENCE_ASYNC();
    CLUSTER_SYNC();    // both CTAs' PE tiles ready before L0 MMAs

    Pipe pp;
    pp.gmma = 0; pp.gcopy = NBUF - 1; pp.gfwd = 0; pp.lpar = 0;
    #pragma unroll
    for (int b = 0; b < NBUF; ++b) { pp.rpf[b] = 0; pp.pm[b] = 0; pp.pc[b] = 0; }

    //                            nch step  bias     relu epi sig
    run_layer(smem, sb, tmem, rank,  4, 0,  g1_0_b,  1, 1, 0, pp);
    run_layer(smem, sb, tmem, rank, 16, 4,  g1_1_b,  1, 1, 0, pp);
    run_layer(smem, sb, tmem, rank, 16, 4,  g1_2_b,  1, 1, 0, pp);
    run_layer(smem, sb, tmem, rank, 16, 4,  g1_3_b,  1, 1, 0, pp);
    run_layer(smem, sb, tmem, rank, 16, 4,  g1_4_b,  0, 1, 0, pp);
    run_layer(smem, sb, tmem, rank, 20, 0,  g2_0_b,  1, 1, 0, pp);

    // pe_d -> cols [24,63): L5 fully drained (layer barrier) and its epilogue
    // + cluster sync completed, so no MMA still reads pe_x.
    {
        const float* dr = dirg + (size_t)(row0 + r) * 3;
        float d0 = dr[0], d1 = dr[1], d2 = dr[2];
        if (p == 0) {
            a_store(Ahi, Alo, r, 24, d0);
            a_store(Ahi, Alo, r, 25, d1);
            a_store(Ahi, Alo, r, 26, d2);
        }
        for (int l = p; l < 6; l += 4) {
            float f = (float)(1 << l);
            float s, c;
            sincosf(d0 * f, &s, &c); a_store(Ahi, Alo, r, 27 + 6 * l + 0, s); a_store(Ahi, Alo, r, 30 + 6 * l + 0, c);
            sincosf(d1 * f, &s, &c); a_store(Ahi, Alo, r, 27 + 6 * l + 1, s); a_store(Ahi, Alo, r, 30 + 6 * l + 1, c);
            sincosf(d2 * f, &s, &c); a_store(Ahi, Alo, r, 27 + 6 * l + 2, s); a_store(Ahi, Alo, r, 30 + 6 * l + 2, c);
        }
        FENCE_ASYNC();
    }
    CLUSTER_SYNC();    // pe_d visible to the pair before L6 MMAs

    run_layer(smem, sb, tmem, rank, 16, 4,  g2_1_b,  1, 1, 0, pp);
    run_layer(smem, sb, tmem, rank, 16, 4,  g2_2_b,  0, 1, 1, pp);  // feat2 + sigma fold
    run_layer(smem, sb, tmem, rank, 20, 0,  c_0_b,   0, 0, 0, pp);  // c_0 preact -> D

    __syncthreads();
    TC_FENCE_AFTER();

    // stage rgb head weights into (now-idle) B region
    float* SWM = (float*)(smem + B_OFF);
    for (int i = tid; i < 768; i += TPB) SWM[i] = __ldg(c_1_W + i);
    if (tid == 0) {
        SWM[768] = sig_b[0];
        SWM[769] = c_1_b[0]; SWM[770] = c_1_b[1]; SWM[771] = c_1_b[2];
    }
    float* PART = (float*)(smem + B_OFF + 8192);
    __syncthreads();

    // rgb head, all 16 warps: col group cb = w>>2, rows (w&3)*32+lane (local)
    {
        const int cb = w >> 2;
        const int rr = (w & 3) * 32 + lane;
        float o0 = 0.f, o1 = 0.f, o2 = 0.f;
        #pragma unroll
        for (int blk = 0; blk < 2; ++blk) {
            const int kb = cb * 64 + blk * 32;
            float4 bb[8];
            #pragma unroll
            for (int q = 0; q < 8; ++q) bb[q] = __ldg((const float4*)c_0_b + kb / 4 + q);
            uint32_t rg[32];
            TC_LD_X32(rg, tmem + kb);
            TC_WAIT_LD();
            #pragma unroll
            for (int i = 0; i < 32; ++i) {
                int k = kb + i;
                float bias_v = ((const float*)bb)[i];
                float f = fmaxf(__uint_as_float(rg[i]) + bias_v, 0.f);
                o0 += f * SWM[3 * k + 0];
                o1 += f * SWM[3 * k + 1];
                o2 += f * SWM[3 * k + 2];
            }
        }
        float* pd = PART + (cb * 128 + rr) * 4;
        pd[0] = o0; pd[1] = o1; pd[2] = o2;
    }
    __syncthreads();
    if (w < 4) {
        const int rr = w * 32 + lane;
        float o0 = 0.f, o1 = 0.f, o2 = 0.f;
        #pragma unroll
        for (int g = 0; g < 4; ++g) {
            const float* pd = PART + (g * 128 + rr) * 4;
            o0 += pd[0]; o1 += pd[1]; o2 += pd[2];
        }
        float sig = ((const float*)(smem + SIGA_OFF))[rr] + SWM[768];
        float4 o = make_float4(o0 + SWM[769], o1 + SWM[770], o2 + SWM[771], sig);
        *(float4*)(out + (size_t)(row0 + rr) * 4) = o;
        TC_FENCE_BEFORE();
    }
    __syncthreads();
    CLUSTER_SYNC();    // no CTA tears down while its pair may still run MMAs
    if (w == 0) { TC_RELINQ2(); TC_DEALLOC2(tmem, 256); }
    CLUSTER_SYNC();
}

// ---------------------------------------------------------------- launch ----
extern "C" void kernel_launch(void* const* d_in, const int* in_sizes, int n_in,
                              void* d_out, int out_size)
{
    const float* x      = (const float*)d_in[0];
    const float* dirg   = (const float*)d_in[1];
    const float* g1_0_W = (const float*)d_in[2];  const float* g1_0_b = (const float*)d_in[3];
    const float* g1_1_W = (const float*)d_in[4];  const float* g1_1_b = (const float*)d_in[5];
    const float* g1_2_W = (const float*)d_in[6];  const float* g1_2_b = (const float*)d_in[7];
    const float* g1_3_W = (const float*)d_in[8];  const float* g1_3_b = (const float*)d_in[9];
    const float* g1_4_W = (const float*)d_in[10]; const float* g1_4_b = (const float*)d_in[11];
    const float* g2_0_W = (const float*)d_in[12]; const float* g2_0_b = (const float*)d_in[13];
    const float* g2_1_W = (const float*)d_in[14]; const float* g2_1_b = (const float*)d_in[15];
    const float* g2_2_W = (const float*)d_in[16]; const float* g2_2_b = (const float*)d_in[17];
    const float* c_0_W  = (const float*)d_in[18]; const float* c_0_b  = (const float*)d_in[19];
    const float* c_1_W  = (const float*)d_in[20]; const float* c_1_b  = (const float*)d_in[21];
    const float* sig_W  = (const float*)d_in[22]; const float* sig_b  = (const float*)d_in[23];
    float* out = (float*)d_out;

    const int N = in_sizes[0] / 3;           // 262144
    const int nblocks = N / MROWS;           // 2048 (even -> 1024 clusters of 2)

    dim3 pgrid(320, 9);
    nerf_prepass<<<pgrid, 256>>>(g1_0_W, g1_1_W, g1_2_W, g1_3_W, g1_4_W,
                                 g2_0_W, g2_1_W, g2_2_W, c_0_W);

    cudaFuncSetAttribute(nerf_main, cudaFuncAttributeMaxDynamicSharedMemorySize, SMEM_BYTES);
    nerf_main<<<nblocks, TPB, SMEM_BYTES>>>(
        x, dirg,
        g1_0_b, g1_1_b, g1_2_b, g1_3_b, g1_4_b,
        g2_0_b, g2_1_b, g2_2_b,
        c_0_b, c_1_W, c_1_b,
        sig_W, sig_b,
        out);
}